// round 3
// baseline (speedup 1.0000x reference)
#include <cuda_runtime.h>
#include <math_constants.h>

// Gate_8108898255611: router gate, eval-mode token_choice.
// Forward value of the STE mix is exactly the one-hot, so
//   output 0 (weights) == 1.0f for every token (ROUTE_SCALE = 1).
//   output 1 (indices) == argmax_e sum_d x[t,d] * w[e,d]
// Harness output buffer is float32 throughout -> indices stored as float VALUES.

constexpr int T_TOK   = 16384;
constexpr int DIM     = 4096;
constexpr int NEXP    = 256;
constexpr int BM      = 128;   // tokens per block
constexpr int BK      = 16;    // k-slice
constexpr int NTHREADS = 512;  // 16 warps: warp = 8 tokens x 256 experts
constexpr int XS_STRIDE = BM + 4;

__global__ __launch_bounds__(NTHREADS, 1)
void gate_kernel(const float* __restrict__ x,
                 const float* __restrict__ w,
                 float* __restrict__ out)
{
    __shared__ float Xs[BK][XS_STRIDE];  // [k][token]  (transposed)
    __shared__ float Ws[BK][NEXP];       // [k][expert] (transposed)

    const int tid = threadIdx.x;
    const int tx  = tid & 31;   // lane: covers experts tx*8 .. tx*8+7
    const int ty  = tid >> 5;   // warp: owns tokens ty*8 .. ty*8+7
    const int t0  = blockIdx.x * BM;

    float acc[8][8];
#pragma unroll
    for (int i = 0; i < 8; i++)
#pragma unroll
        for (int j = 0; j < 8; j++) acc[i][j] = 0.f;

    // x tile load mapping: 128 rows x 16 cols, one float4 per thread
    const int xr = tid >> 2;             // token row 0..127
    const int xc = (tid & 3) << 2;       // k offset 0,4,8,12

    // w tile load mapping: 256 experts x 16 k, two float4 per thread
    const int it1 = tid + NTHREADS;
    const int we0 = tid >> 2, wk0 = (tid & 3) << 2;
    const int we1 = it1 >> 2, wk1 = (it1 & 3) << 2;

    const float* xrow  = x + (size_t)(t0 + xr) * DIM + xc;
    const float* wrow0 = w + (size_t)we0 * DIM + wk0;
    const float* wrow1 = w + (size_t)we1 * DIM + wk1;

    for (int k0 = 0; k0 < DIM; k0 += BK) {
        // issue global loads before the WAR barrier to overlap latency
        float4 xv  = *reinterpret_cast<const float4*>(xrow  + k0);
        float4 wv0 = *reinterpret_cast<const float4*>(wrow0 + k0);
        float4 wv1 = *reinterpret_cast<const float4*>(wrow1 + k0);

        __syncthreads();  // previous iteration's smem reads done
        Xs[xc + 0][xr] = xv.x;
        Xs[xc + 1][xr] = xv.y;
        Xs[xc + 2][xr] = xv.z;
        Xs[xc + 3][xr] = xv.w;
        Ws[wk0 + 0][we0] = wv0.x;
        Ws[wk0 + 1][we0] = wv0.y;
        Ws[wk0 + 2][we0] = wv0.z;
        Ws[wk0 + 3][we0] = wv0.w;
        Ws[wk1 + 0][we1] = wv1.x;
        Ws[wk1 + 1][we1] = wv1.y;
        Ws[wk1 + 2][we1] = wv1.z;
        Ws[wk1 + 3][we1] = wv1.w;
        __syncthreads();

#pragma unroll
        for (int k = 0; k < BK; k++) {
            float a[8], b[8];
            // Xs reads: all lanes in warp share ty -> broadcast (free)
            *reinterpret_cast<float4*>(&a[0]) =
                *reinterpret_cast<const float4*>(&Xs[k][ty * 8]);
            *reinterpret_cast<float4*>(&a[4]) =
                *reinterpret_cast<const float4*>(&Xs[k][ty * 8 + 4]);
            // Ws reads: lanes read disjoint 32B chunks -> conflict-free phases
            *reinterpret_cast<float4*>(&b[0]) =
                *reinterpret_cast<const float4*>(&Ws[k][tx * 8]);
            *reinterpret_cast<float4*>(&b[4]) =
                *reinterpret_cast<const float4*>(&Ws[k][tx * 8 + 4]);
#pragma unroll
            for (int i = 0; i < 8; i++)
#pragma unroll
                for (int j = 0; j < 8; j++)
                    acc[i][j] = fmaf(a[i], b[j], acc[i][j]);
        }
    }

    // Epilogue: per-token argmax over all 256 experts; weight is constant 1.0.
#pragma unroll
    for (int i = 0; i < 8; i++) {
        float m  = -CUDART_INF_F;
        int  arg = 0;
#pragma unroll
        for (int j = 0; j < 8; j++) {
            if (acc[i][j] > m) { m = acc[i][j]; arg = tx * 8 + j; }
        }
        // warp argmax reduce, lowest index wins ties (matches jnp.argmax)
#pragma unroll
        for (int off = 16; off > 0; off >>= 1) {
            float om = __shfl_xor_sync(0xffffffffu, m, off);
            int   oa = __shfl_xor_sync(0xffffffffu, arg, off);
            if (om > m || (om == m && oa < arg)) { m = om; arg = oa; }
        }
        if (tx == 0) {
            int t = t0 + ty * 8 + i;
            out[t]         = 1.0f;        // STE forward value == one-hot at argmax
            out[T_TOK + t] = (float)arg;  // index as float VALUE (f32 output buffer)
        }
    }
}

extern "C" void kernel_launch(void* const* d_in, const int* in_sizes, int n_in,
                              void* d_out, int out_size) {
    const float* x = (const float*)d_in[0];   // [16384, 4096] f32
    const float* w = (const float*)d_in[1];   // [256, 4096]  f32
    (void)in_sizes; (void)n_in; (void)out_size;

    gate_kernel<<<T_TOK / BM, NTHREADS>>>(x, w, (float*)d_out);
}

// round 5
// speedup vs baseline: 2.0298x; 2.0298x over previous
#include <cuda_runtime.h>
#include <cuda_bf16.h>
#include <cstdint>

// Gate_8108898255611 — router gate via mma.sync bf16x3 (base compute_103 target:
// tcgen05 unavailable in this toolchain, legacy HMMA path used instead).
//   out[0:T)  = 1.0f (STE forward == one-hot)
//   out[T:2T) = argmax_e <x_t, w_e> as float
// bf16 hi/lo split, 3 chains (hi*hi + hi*lo + lo*hi), fp32 accum.
// Near-ties (gap < TAU) exactly rescored in fp32 from global memory.

constexpr int T_TOK = 16384;
constexpr int DIM   = 4096;
constexpr int NEXP  = 256;
constexpr int BM    = 128;            // tokens per CTA
constexpr int KC    = 64;             // k per chunk (128B bf16 rows)
constexpr int NCHUNK = DIM / KC;      // 64
constexpr int NTHREADS = 512;         // 16 warps, 4x4 warp grid
constexpr float TAU = 1e-3f;

constexpr int A_SZ  = BM * 128;       // 16KB  (128 rows x 128B)
constexpr int B_SZ  = NEXP * 128;     // 32KB
constexpr int STAGE = 2 * A_SZ + 2 * B_SZ;    // 96KB (Ahi,Alo,Bhi,Blo)
constexpr int SMEM_TOTAL = 2 * STAGE;         // 192KB
constexpr int SC_STRIDE = 257;

__device__ __nv_bfloat16 g_w_hi[NEXP * DIM];
__device__ __nv_bfloat16 g_w_lo[NEXP * DIM];

// ---------------- helpers ----------------
__device__ __forceinline__ uint32_t smem_u32(const void* p) {
    uint32_t a;
    asm("{ .reg .u64 t; cvta.to.shared.u64 t, %1; cvt.u32.u64 %0, t; }"
        : "=r"(a) : "l"(p));
    return a;
}
__device__ __forceinline__ uint32_t sw128(uint32_t off) {
    return off ^ ((off >> 3) & 0x70);
}
__device__ __forceinline__ uint32_t pack_bf2(__nv_bfloat16 a, __nv_bfloat16 b) {
    return (uint32_t)__bfloat16_as_ushort(a) | ((uint32_t)__bfloat16_as_ushort(b) << 16);
}
__device__ __forceinline__ void ldsm4(uint32_t* r, uint32_t addr) {
    asm volatile("ldmatrix.sync.aligned.m8n8.x4.shared.b16 {%0,%1,%2,%3}, [%4];"
                 : "=r"(r[0]), "=r"(r[1]), "=r"(r[2]), "=r"(r[3]) : "r"(addr));
}
__device__ __forceinline__ void mma_bf16(float* d, const uint32_t* a,
                                         uint32_t b0, uint32_t b1) {
    asm volatile(
        "mma.sync.aligned.m16n8k16.row.col.f32.bf16.bf16.f32 "
        "{%0,%1,%2,%3}, {%4,%5,%6,%7}, {%8,%9}, {%0,%1,%2,%3};"
        : "+f"(d[0]), "+f"(d[1]), "+f"(d[2]), "+f"(d[3])
        : "r"(a[0]), "r"(a[1]), "r"(a[2]), "r"(a[3]), "r"(b0), "r"(b1));
}

// ---------------- w pre-convert ----------------
__global__ void wconv_kernel(const float* __restrict__ w) {
    int n4 = NEXP * DIM / 4;
    for (int i = blockIdx.x * blockDim.x + threadIdx.x; i < n4;
         i += gridDim.x * blockDim.x) {
        float4 v = reinterpret_cast<const float4*>(w)[i];
        __nv_bfloat16 h0 = __float2bfloat16(v.x), h1 = __float2bfloat16(v.y);
        __nv_bfloat16 h2 = __float2bfloat16(v.z), h3 = __float2bfloat16(v.w);
        float l0 = v.x - __bfloat162float(h0), l1 = v.y - __bfloat162float(h1);
        float l2 = v.z - __bfloat162float(h2), l3 = v.w - __bfloat162float(h3);
        reinterpret_cast<uint2*>(g_w_hi)[i] =
            make_uint2(pack_bf2(h0, h1), pack_bf2(h2, h3));
        reinterpret_cast<uint2*>(g_w_lo)[i] =
            make_uint2(pack_bf2(__float2bfloat16(l0), __float2bfloat16(l1)),
                       pack_bf2(__float2bfloat16(l2), __float2bfloat16(l3)));
    }
}

// ---------------- main kernel ----------------
__global__ __launch_bounds__(NTHREADS, 1)
void gate_mma_kernel(const float* __restrict__ x,
                     const float* __restrict__ w,
                     float* __restrict__ out)
{
    extern __shared__ char smem[];
    const uint32_t sb = smem_u32(smem);
    const int tid  = threadIdx.x;
    const int lane = tid & 31;
    const int wid  = tid >> 5;
    const int wm   = wid >> 2;   // 0..3 -> 32-row strip
    const int wn   = wid & 3;    // 0..3 -> 64-col strip
    const int t0   = blockIdx.x * BM;
    const float* xbase = x + (size_t)t0 * DIM;

    float acc[2][8][4];
#pragma unroll
    for (int i = 0; i < 2; i++)
#pragma unroll
        for (int j = 0; j < 8; j++)
#pragma unroll
            for (int q = 0; q < 4; q++) acc[i][j][q] = 0.f;

    float4 xv[4];  // prefetched x chunk (fp32)

    auto load_x = [&](int k0) {
#pragma unroll
        for (int t = 0; t < 4; ++t) {
            const int i = tid + t * NTHREADS;
            const int r = i >> 4, c4 = (i & 15) << 2;
            xv[t] = *reinterpret_cast<const float4*>(xbase + (size_t)r * DIM + k0 + c4);
        }
    };
    auto sts_x = [&](int s) {
        char* aH = smem + s * STAGE;
        char* aL = aH + A_SZ;
#pragma unroll
        for (int t = 0; t < 4; ++t) {
            const int i = tid + t * NTHREADS;
            const int r = i >> 4, c4 = (i & 15) << 2;
            const float4 v = xv[t];
            __nv_bfloat16 h0 = __float2bfloat16(v.x), h1 = __float2bfloat16(v.y);
            __nv_bfloat16 h2 = __float2bfloat16(v.z), h3 = __float2bfloat16(v.w);
            float l0 = v.x - __bfloat162float(h0), l1 = v.y - __bfloat162float(h1);
            float l2 = v.z - __bfloat162float(h2), l3 = v.w - __bfloat162float(h3);
            const uint32_t off = sw128((uint32_t)(r * 128 + c4 * 2));
            *reinterpret_cast<uint2*>(aH + off) =
                make_uint2(pack_bf2(h0, h1), pack_bf2(h2, h3));
            *reinterpret_cast<uint2*>(aL + off) =
                make_uint2(pack_bf2(__float2bfloat16(l0), __float2bfloat16(l1)),
                           pack_bf2(__float2bfloat16(l2), __float2bfloat16(l3)));
        }
    };
    auto load_store_w = [&](int s, int k0) {
        char* bH = smem + s * STAGE + 2 * A_SZ;
        char* bL = bH + B_SZ;
#pragma unroll
        for (int t = 0; t < 4; ++t) {
            const int i = tid + t * NTHREADS;
            const int r = i >> 3, c16 = (i & 7) << 4;
            const uint32_t off = sw128((uint32_t)(r * 128 + c16));
            const size_t gs = ((size_t)r * DIM + k0) * 2 + c16;
            uint4 vh = *reinterpret_cast<const uint4*>((const char*)g_w_hi + gs);
            uint4 vl = *reinterpret_cast<const uint4*>((const char*)g_w_lo + gs);
            *reinterpret_cast<uint4*>(bH + off) = vh;
            *reinterpret_cast<uint4*>(bL + off) = vl;
        }
    };
    auto compute = [&](int s) {
        const uint32_t aHb = sb + s * STAGE;
        const uint32_t aLb = aHb + A_SZ;
        const uint32_t bHb = aHb + 2 * A_SZ;
        const uint32_t bLb = bHb + B_SZ;
#pragma unroll
        for (int k = 0; k < 4; ++k) {
            const int kb = k * 32;
            uint32_t aH[2][4], aL[2][4];
#pragma unroll
            for (int mi = 0; mi < 2; ++mi) {
                const int row = wm * 32 + mi * 16 + (lane & 15);
                const int byt = ((lane >> 4) << 4) + kb;
                const uint32_t off = sw128((uint32_t)(row * 128 + byt));
                ldsm4(aH[mi], aHb + off);
                ldsm4(aL[mi], aLb + off);
            }
#pragma unroll
            for (int t = 0; t < 4; ++t) {
                const int nrow = wn * 64 + t * 16 + (lane & 7) + ((lane >> 4) << 3);
                const int byt  = kb + (((lane >> 3) & 1) << 4);
                const uint32_t off = sw128((uint32_t)(nrow * 128 + byt));
                uint32_t bH[4], bL[4];
                ldsm4(bH, bHb + off);
                ldsm4(bL, bLb + off);
#pragma unroll
                for (int mi = 0; mi < 2; ++mi) {
                    mma_bf16(acc[mi][2 * t],     aH[mi], bH[0], bH[1]);  // hi*hi
                    mma_bf16(acc[mi][2 * t + 1], aH[mi], bH[2], bH[3]);
                    mma_bf16(acc[mi][2 * t],     aH[mi], bL[0], bL[1]);  // hi*lo
                    mma_bf16(acc[mi][2 * t + 1], aH[mi], bL[2], bL[3]);
                    mma_bf16(acc[mi][2 * t],     aL[mi], bH[0], bH[1]);  // lo*hi
                    mma_bf16(acc[mi][2 * t + 1], aL[mi], bH[2], bH[3]);
                }
            }
        }
    };

    // ---- pipelined mainloop: 2 smem stages, x prefetched in regs ----
    load_x(0);
    for (int c = 0; c < NCHUNK; ++c) {
        const int s = c & 1;
        sts_x(s);
        load_store_w(s, c * KC);
        __syncthreads();                      // stage s ready; prior compute done
        if (c + 1 < NCHUNK) load_x((c + 1) * KC);
        compute(s);
    }

    // ---- epilogue: scores -> smem, per-token argmax + exact rescore ----
    __syncthreads();
    float* sc = reinterpret_cast<float*>(smem);
#pragma unroll
    for (int mi = 0; mi < 2; ++mi)
#pragma unroll
        for (int nj = 0; nj < 8; ++nj) {
            const int r  = wm * 32 + mi * 16 + (lane >> 2);
            const int cc = wn * 64 + nj * 8 + ((lane & 3) << 1);
            sc[r * SC_STRIDE + cc]           = acc[mi][nj][0];
            sc[r * SC_STRIDE + cc + 1]       = acc[mi][nj][1];
            sc[(r + 8) * SC_STRIDE + cc]     = acc[mi][nj][2];
            sc[(r + 8) * SC_STRIDE + cc + 1] = acc[mi][nj][3];
        }
    __syncthreads();

    if (wid < 4) {
        const int r = wid * 32 + lane;     // token row in tile
        const int t = t0 + r;
        float m1 = -__int_as_float(0x7f800000);
        float m2 = m1;
        int i1 = 0;
        for (int j = 0; j < NEXP; ++j) {
            const float v = sc[r * SC_STRIDE + j];
            if (v > m1) { m2 = m1; m1 = v; i1 = j; }
            else if (v > m2) { m2 = v; }
        }
        if (m1 - m2 < TAU) {
            // exact fp32 rescore of all candidates within TAU of max
            float best = m1;
            int bi = i1;
            bool have = false;
            const float4* xa = reinterpret_cast<const float4*>(x + (size_t)t * DIM);
            for (int j = 0; j < NEXP; ++j) {
                if (sc[r * SC_STRIDE + j] >= m1 - TAU) {
                    const float4* wb =
                        reinterpret_cast<const float4*>(w + (size_t)j * DIM);
                    float s0 = 0.f, s1 = 0.f, s2 = 0.f, s3 = 0.f;
                    for (int kk = 0; kk < DIM / 4; ++kk) {
                        float4 va = xa[kk], vb = wb[kk];
                        s0 = fmaf(va.x, vb.x, s0);
                        s1 = fmaf(va.y, vb.y, s1);
                        s2 = fmaf(va.z, vb.z, s2);
                        s3 = fmaf(va.w, vb.w, s3);
                    }
                    const float ex = (s0 + s1) + (s2 + s3);
                    if (!have || ex > best) { have = true; best = ex; bi = j; }
                }
            }
            i1 = bi;
        }
        out[t]         = 1.0f;
        out[T_TOK + t] = (float)i1;
    }
}

extern "C" void kernel_launch(void* const* d_in, const int* in_sizes, int n_in,
                              void* d_out, int out_size) {
    const float* x = (const float*)d_in[0];   // [16384, 4096] f32
    const float* w = (const float*)d_in[1];   // [256, 4096]  f32
    (void)in_sizes; (void)n_in; (void)out_size;

    cudaFuncSetAttribute(gate_mma_kernel,
                         cudaFuncAttributeMaxDynamicSharedMemorySize, SMEM_TOTAL);

    wconv_kernel<<<256, 256>>>(w);
    gate_mma_kernel<<<T_TOK / BM, NTHREADS, SMEM_TOTAL>>>(x, w, (float*)d_out);
}

// round 6
// speedup vs baseline: 2.1780x; 1.0730x over previous
#include <cuda_runtime.h>
#include <cuda_bf16.h>
#include <cstdint>

// Gate_8108898255611 — router gate via mma.sync bf16x3 (base compute_103 target).
//   out[0:T)  = 1.0f (STE forward == one-hot)
//   out[T:2T) = argmax_e <x_t, w_e> as float
// bf16 hi/lo split, 3 chains (hi*hi + hi*lo + lo*hi), fp32 accum.
// Near-ties (gap < TAU) exactly rescored in fp32 from global memory.
// R6: w staged via cp.async.cg (no reg round-trip), single-barrier pipeline.

constexpr int T_TOK = 16384;
constexpr int DIM   = 4096;
constexpr int NEXP  = 256;
constexpr int BM    = 128;            // tokens per CTA
constexpr int KC    = 64;             // k per chunk (128B bf16 rows)
constexpr int NCHUNK = DIM / KC;      // 64
constexpr int NTHREADS = 512;         // 16 warps, 4x4 warp grid
constexpr float TAU = 1e-3f;

constexpr int A_SZ  = BM * 128;       // 16KB  (128 rows x 128B)
constexpr int B_SZ  = NEXP * 128;     // 32KB
constexpr int STAGE = 2 * A_SZ + 2 * B_SZ;    // 96KB (Ahi,Alo,Bhi,Blo)
constexpr int SMEM_TOTAL = 2 * STAGE;         // 192KB
constexpr int SC_STRIDE = 257;

__device__ __nv_bfloat16 g_w_hi[NEXP * DIM];
__device__ __nv_bfloat16 g_w_lo[NEXP * DIM];

// ---------------- helpers ----------------
__device__ __forceinline__ uint32_t smem_u32(const void* p) {
    uint32_t a;
    asm("{ .reg .u64 t; cvta.to.shared.u64 t, %1; cvt.u32.u64 %0, t; }"
        : "=r"(a) : "l"(p));
    return a;
}
__device__ __forceinline__ uint32_t sw128(uint32_t off) {
    return off ^ ((off >> 3) & 0x70);
}
__device__ __forceinline__ uint32_t pack_bf2(__nv_bfloat16 a, __nv_bfloat16 b) {
    return (uint32_t)__bfloat16_as_ushort(a) | ((uint32_t)__bfloat16_as_ushort(b) << 16);
}
__device__ __forceinline__ void ldsm4(uint32_t* r, uint32_t addr) {
    asm volatile("ldmatrix.sync.aligned.m8n8.x4.shared.b16 {%0,%1,%2,%3}, [%4];"
                 : "=r"(r[0]), "=r"(r[1]), "=r"(r[2]), "=r"(r[3]) : "r"(addr));
}
__device__ __forceinline__ void mma_bf16(float* d, const uint32_t* a,
                                         uint32_t b0, uint32_t b1) {
    asm volatile(
        "mma.sync.aligned.m16n8k16.row.col.f32.bf16.bf16.f32 "
        "{%0,%1,%2,%3}, {%4,%5,%6,%7}, {%8,%9}, {%0,%1,%2,%3};"
        : "+f"(d[0]), "+f"(d[1]), "+f"(d[2]), "+f"(d[3])
        : "r"(a[0]), "r"(a[1]), "r"(a[2]), "r"(a[3]), "r"(b0), "r"(b1));
}
__device__ __forceinline__ void cp_async16(uint32_t dst, const void* src) {
    asm volatile("cp.async.cg.shared.global [%0], [%1], 16;"
                 :: "r"(dst), "l"(src) : "memory");
}
__device__ __forceinline__ void cp_commit() {
    asm volatile("cp.async.commit_group;" ::: "memory");
}
__device__ __forceinline__ void cp_wait_all() {
    asm volatile("cp.async.wait_group 0;" ::: "memory");
}

// ---------------- w pre-convert ----------------
__global__ void wconv_kernel(const float* __restrict__ w) {
    int n4 = NEXP * DIM / 4;
    for (int i = blockIdx.x * blockDim.x + threadIdx.x; i < n4;
         i += gridDim.x * blockDim.x) {
        float4 v = reinterpret_cast<const float4*>(w)[i];
        __nv_bfloat16 h0 = __float2bfloat16(v.x), h1 = __float2bfloat16(v.y);
        __nv_bfloat16 h2 = __float2bfloat16(v.z), h3 = __float2bfloat16(v.w);
        float l0 = v.x - __bfloat162float(h0), l1 = v.y - __bfloat162float(h1);
        float l2 = v.z - __bfloat162float(h2), l3 = v.w - __bfloat162float(h3);
        reinterpret_cast<uint2*>(g_w_hi)[i] =
            make_uint2(pack_bf2(h0, h1), pack_bf2(h2, h3));
        reinterpret_cast<uint2*>(g_w_lo)[i] =
            make_uint2(pack_bf2(__float2bfloat16(l0), __float2bfloat16(l1)),
                       pack_bf2(__float2bfloat16(l2), __float2bfloat16(l3)));
    }
}

// ---------------- main kernel ----------------
__global__ __launch_bounds__(NTHREADS, 1)
void gate_mma_kernel(const float* __restrict__ x,
                     const float* __restrict__ w,
                     float* __restrict__ out)
{
    extern __shared__ char smem[];
    const uint32_t sb = smem_u32(smem);
    const int tid  = threadIdx.x;
    const int lane = tid & 31;
    const int wid  = tid >> 5;
    const int wm   = wid >> 2;   // 0..3 -> 32-row strip
    const int wn   = wid & 3;    // 0..3 -> 64-col strip
    const int t0   = blockIdx.x * BM;
    const float* xbase = x + (size_t)t0 * DIM;

    float acc[2][8][4];
#pragma unroll
    for (int i = 0; i < 2; i++)
#pragma unroll
        for (int j = 0; j < 8; j++)
#pragma unroll
            for (int q = 0; q < 4; q++) acc[i][j][q] = 0.f;

    float4 xv[4];  // prefetched x chunk (fp32)

    auto load_x = [&](int k0) {
#pragma unroll
        for (int t = 0; t < 4; ++t) {
            const int i = tid + t * NTHREADS;
            const int r = i >> 4, c4 = (i & 15) << 2;
            xv[t] = *reinterpret_cast<const float4*>(xbase + (size_t)r * DIM + k0 + c4);
        }
    };
    auto sts_x = [&](int s) {
        char* aH = smem + s * STAGE;
        char* aL = aH + A_SZ;
#pragma unroll
        for (int t = 0; t < 4; ++t) {
            const int i = tid + t * NTHREADS;
            const int r = i >> 4, c4 = (i & 15) << 2;
            const float4 v = xv[t];
            __nv_bfloat16 h0 = __float2bfloat16(v.x), h1 = __float2bfloat16(v.y);
            __nv_bfloat16 h2 = __float2bfloat16(v.z), h3 = __float2bfloat16(v.w);
            float l0 = v.x - __bfloat162float(h0), l1 = v.y - __bfloat162float(h1);
            float l2 = v.z - __bfloat162float(h2), l3 = v.w - __bfloat162float(h3);
            const uint32_t off = sw128((uint32_t)(r * 128 + c4 * 2));
            *reinterpret_cast<uint2*>(aH + off) =
                make_uint2(pack_bf2(h0, h1), pack_bf2(h2, h3));
            *reinterpret_cast<uint2*>(aL + off) =
                make_uint2(pack_bf2(__float2bfloat16(l0), __float2bfloat16(l1)),
                           pack_bf2(__float2bfloat16(l2), __float2bfloat16(l3)));
        }
    };
    auto cpasync_w = [&](int s, int k0) {
        const uint32_t bH = sb + s * STAGE + 2 * A_SZ;
        const uint32_t bL = bH + B_SZ;
#pragma unroll
        for (int t = 0; t < 4; ++t) {
            const int i = tid + t * NTHREADS;
            const int r = i >> 3, c16 = (i & 7) << 4;
            const uint32_t off = sw128((uint32_t)(r * 128 + c16));
            const size_t gs = ((size_t)r * DIM + k0) * 2 + c16;
            cp_async16(bH + off, (const char*)g_w_hi + gs);
            cp_async16(bL + off, (const char*)g_w_lo + gs);
        }
        cp_commit();
    };
    auto compute = [&](int s) {
        const uint32_t aHb = sb + s * STAGE;
        const uint32_t aLb = aHb + A_SZ;
        const uint32_t bHb = aHb + 2 * A_SZ;
        const uint32_t bLb = bHb + B_SZ;
#pragma unroll
        for (int k = 0; k < 4; ++k) {
            const int kb = k * 32;
            uint32_t aH[2][4], aL[2][4];
#pragma unroll
            for (int mi = 0; mi < 2; ++mi) {
                const int row = wm * 32 + mi * 16 + (lane & 15);
                const int byt = ((lane >> 4) << 4) + kb;
                const uint32_t off = sw128((uint32_t)(row * 128 + byt));
                ldsm4(aH[mi], aHb + off);
                ldsm4(aL[mi], aLb + off);
            }
#pragma unroll
            for (int t = 0; t < 4; ++t) {
                const int nrow = wn * 64 + t * 16 + (lane & 7) + ((lane >> 4) << 3);
                const int byt  = kb + (((lane >> 3) & 1) << 4);
                const uint32_t off = sw128((uint32_t)(nrow * 128 + byt));
                uint32_t bH[4], bL[4];
                ldsm4(bH, bHb + off);
                ldsm4(bL, bLb + off);
#pragma unroll
                for (int mi = 0; mi < 2; ++mi) {
                    mma_bf16(acc[mi][2 * t],     aH[mi], bH[0], bH[1]);  // hi*hi
                    mma_bf16(acc[mi][2 * t + 1], aH[mi], bH[2], bH[3]);
                    mma_bf16(acc[mi][2 * t],     aH[mi], bL[0], bL[1]);  // hi*lo
                    mma_bf16(acc[mi][2 * t + 1], aH[mi], bL[2], bL[3]);
                    mma_bf16(acc[mi][2 * t],     aL[mi], bH[0], bH[1]);  // lo*hi
                    mma_bf16(acc[mi][2 * t + 1], aL[mi], bH[2], bH[3]);
                }
            }
        }
    };

    // ---- pipelined mainloop ----
    // iter c: [cp.wait(w chunk c) | STS x(s) | bar | cp.async w(c+1) | LDG x(c+1) | MMA(s)]
    // Single barrier per chunk; WAR on stage s protected by bar(c-1) (all warps
    // finish compute(s)@c-2 before passing it), cp.async into s^1 issued after
    // bar(c) which follows compute(s^1)@c-1 in program order for every warp.
    load_x(0);
    cpasync_w(0, 0);
    for (int c = 0; c < NCHUNK; ++c) {
        const int s = c & 1;
        cp_wait_all();                    // w for chunk c resident
        sts_x(s);
        __syncthreads();
        if (c + 1 < NCHUNK) {
            cpasync_w(s ^ 1, (c + 1) * KC);
            load_x((c + 1) * KC);
        }
        compute(s);
    }

    // ---- epilogue: scores -> smem, per-token argmax + exact rescore ----
    __syncthreads();
    float* sc = reinterpret_cast<float*>(smem);
#pragma unroll
    for (int mi = 0; mi < 2; ++mi)
#pragma unroll
        for (int nj = 0; nj < 8; ++nj) {
            const int r  = wm * 32 + mi * 16 + (lane >> 2);
            const int cc = wn * 64 + nj * 8 + ((lane & 3) << 1);
            sc[r * SC_STRIDE + cc]           = acc[mi][nj][0];
            sc[r * SC_STRIDE + cc + 1]       = acc[mi][nj][1];
            sc[(r + 8) * SC_STRIDE + cc]     = acc[mi][nj][2];
            sc[(r + 8) * SC_STRIDE + cc + 1] = acc[mi][nj][3];
        }
    __syncthreads();

    if (wid < 4) {
        const int r = wid * 32 + lane;     // token row in tile
        const int t = t0 + r;
        float m1 = -__int_as_float(0x7f800000);
        float m2 = m1;
        int i1 = 0;
        for (int j = 0; j < NEXP; ++j) {
            const float v = sc[r * SC_STRIDE + j];
            if (v > m1) { m2 = m1; m1 = v; i1 = j; }
            else if (v > m2) { m2 = v; }
        }
        if (m1 - m2 < TAU) {
            // exact fp32 rescore of all candidates within TAU of max
            float best = m1;
            int bi = i1;
            bool have = false;
            const float4* xa = reinterpret_cast<const float4*>(x + (size_t)t * DIM);
            for (int j = 0; j < NEXP; ++j) {
                if (sc[r * SC_STRIDE + j] >= m1 - TAU) {
                    const float4* wb =
                        reinterpret_cast<const float4*>(w + (size_t)j * DIM);
                    float s0 = 0.f, s1 = 0.f, s2 = 0.f, s3 = 0.f;
                    for (int kk = 0; kk < DIM / 4; ++kk) {
                        float4 va = xa[kk], vb = wb[kk];
                        s0 = fmaf(va.x, vb.x, s0);
                        s1 = fmaf(va.y, vb.y, s1);
                        s2 = fmaf(va.z, vb.z, s2);
                        s3 = fmaf(va.w, vb.w, s3);
                    }
                    const float ex = (s0 + s1) + (s2 + s3);
                    if (!have || ex > best) { have = true; best = ex; bi = j; }
                }
            }
            i1 = bi;
        }
        out[t]         = 1.0f;
        out[T_TOK + t] = (float)i1;
    }
}

extern "C" void kernel_launch(void* const* d_in, const int* in_sizes, int n_in,
                              void* d_out, int out_size) {
    const float* x = (const float*)d_in[0];   // [16384, 4096] f32
    const float* w = (const float*)d_in[1];   // [256, 4096]  f32
    (void)in_sizes; (void)n_in; (void)out_size;

    cudaFuncSetAttribute(gate_mma_kernel,
                         cudaFuncAttributeMaxDynamicSharedMemorySize, SMEM_TOTAL);

    wconv_kernel<<<256, 256>>>(w);
    gate_mma_kernel<<<T_TOK / BM, NTHREADS, SMEM_TOTAL>>>(x, w, (float*)d_out);
}

// round 7
// speedup vs baseline: 2.1949x; 1.0078x over previous
#include <cuda_runtime.h>
#include <cuda_bf16.h>
#include <cstdint>

// Gate_8108898255611 — router gate via mma.sync bf16x3 (base compute_103 target).
//   out[0:T)  = 1.0f (STE forward == one-hot)
//   out[T:2T) = argmax_e <x_t, w_e> as float
// bf16 hi/lo split, 3 chains (hi*hi + hi*lo + lo*hi), fp32 accum.
// Near-ties (gap < TAU) exactly rescored in fp32 from global memory.
// R7: MMA schedule fix — chain-outer order (dependent-acc distance 2->4),
//     non-volatile mma / memory-clobber ldsm so ptxas can schedule.

constexpr int T_TOK = 16384;
constexpr int DIM   = 4096;
constexpr int NEXP  = 256;
constexpr int BM    = 128;            // tokens per CTA
constexpr int KC    = 64;             // k per chunk (128B bf16 rows)
constexpr int NCHUNK = DIM / KC;      // 64
constexpr int NTHREADS = 512;         // 16 warps, 4x4 warp grid
constexpr float TAU = 1e-3f;

constexpr int A_SZ  = BM * 128;       // 16KB  (128 rows x 128B)
constexpr int B_SZ  = NEXP * 128;     // 32KB
constexpr int STAGE = 2 * A_SZ + 2 * B_SZ;    // 96KB (Ahi,Alo,Bhi,Blo)
constexpr int SMEM_TOTAL = 2 * STAGE;         // 192KB
constexpr int SC_STRIDE = 257;

__device__ __nv_bfloat16 g_w_hi[NEXP * DIM];
__device__ __nv_bfloat16 g_w_lo[NEXP * DIM];

// ---------------- helpers ----------------
__device__ __forceinline__ uint32_t smem_u32(const void* p) {
    uint32_t a;
    asm("{ .reg .u64 t; cvta.to.shared.u64 t, %1; cvt.u32.u64 %0, t; }"
        : "=r"(a) : "l"(p));
    return a;
}
__device__ __forceinline__ uint32_t sw128(uint32_t off) {
    return off ^ ((off >> 3) & 0x70);
}
__device__ __forceinline__ uint32_t pack_bf2(__nv_bfloat16 a, __nv_bfloat16 b) {
    return (uint32_t)__bfloat16_as_ushort(a) | ((uint32_t)__bfloat16_as_ushort(b) << 16);
}
// Non-volatile + memory clobber: ptxas may schedule these among MMAs but not
// across barriers / other memory ops.
__device__ __forceinline__ void ldsm4(uint32_t* r, uint32_t addr) {
    asm("ldmatrix.sync.aligned.m8n8.x4.shared.b16 {%0,%1,%2,%3}, [%4];"
        : "=r"(r[0]), "=r"(r[1]), "=r"(r[2]), "=r"(r[3]) : "r"(addr) : "memory");
}
// Non-volatile: ordering carried purely by the "+f" accumulator dependence.
__device__ __forceinline__ void mma_bf16(float* d, const uint32_t* a,
                                         uint32_t b0, uint32_t b1) {
    asm("mma.sync.aligned.m16n8k16.row.col.f32.bf16.bf16.f32 "
        "{%0,%1,%2,%3}, {%4,%5,%6,%7}, {%8,%9}, {%0,%1,%2,%3};"
        : "+f"(d[0]), "+f"(d[1]), "+f"(d[2]), "+f"(d[3])
        : "r"(a[0]), "r"(a[1]), "r"(a[2]), "r"(a[3]), "r"(b0), "r"(b1));
}
__device__ __forceinline__ void cp_async16(uint32_t dst, const void* src) {
    asm volatile("cp.async.cg.shared.global [%0], [%1], 16;"
                 :: "r"(dst), "l"(src) : "memory");
}
__device__ __forceinline__ void cp_commit() {
    asm volatile("cp.async.commit_group;" ::: "memory");
}
__device__ __forceinline__ void cp_wait_all() {
    asm volatile("cp.async.wait_group 0;" ::: "memory");
}

// ---------------- w pre-convert ----------------
__global__ void wconv_kernel(const float* __restrict__ w) {
    int n4 = NEXP * DIM / 4;
    for (int i = blockIdx.x * blockDim.x + threadIdx.x; i < n4;
         i += gridDim.x * blockDim.x) {
        float4 v = reinterpret_cast<const float4*>(w)[i];
        __nv_bfloat16 h0 = __float2bfloat16(v.x), h1 = __float2bfloat16(v.y);
        __nv_bfloat16 h2 = __float2bfloat16(v.z), h3 = __float2bfloat16(v.w);
        float l0 = v.x - __bfloat162float(h0), l1 = v.y - __bfloat162float(h1);
        float l2 = v.z - __bfloat162float(h2), l3 = v.w - __bfloat162float(h3);
        reinterpret_cast<uint2*>(g_w_hi)[i] =
            make_uint2(pack_bf2(h0, h1), pack_bf2(h2, h3));
        reinterpret_cast<uint2*>(g_w_lo)[i] =
            make_uint2(pack_bf2(__float2bfloat16(l0), __float2bfloat16(l1)),
                       pack_bf2(__float2bfloat16(l2), __float2bfloat16(l3)));
    }
}

// ---------------- main kernel ----------------
__global__ __launch_bounds__(NTHREADS, 1)
void gate_mma_kernel(const float* __restrict__ x,
                     const float* __restrict__ w,
                     float* __restrict__ out)
{
    extern __shared__ char smem[];
    const uint32_t sb = smem_u32(smem);
    const int tid  = threadIdx.x;
    const int lane = tid & 31;
    const int wid  = tid >> 5;
    const int wm   = wid >> 2;   // 0..3 -> 32-row strip
    const int wn   = wid & 3;    // 0..3 -> 64-col strip
    const int t0   = blockIdx.x * BM;
    const float* xbase = x + (size_t)t0 * DIM;

    float acc[2][8][4];
#pragma unroll
    for (int i = 0; i < 2; i++)
#pragma unroll
        for (int j = 0; j < 8; j++)
#pragma unroll
            for (int q = 0; q < 4; q++) acc[i][j][q] = 0.f;

    float4 xv[4];  // prefetched x chunk (fp32)

    auto load_x = [&](int k0) {
#pragma unroll
        for (int t = 0; t < 4; ++t) {
            const int i = tid + t * NTHREADS;
            const int r = i >> 4, c4 = (i & 15) << 2;
            xv[t] = *reinterpret_cast<const float4*>(xbase + (size_t)r * DIM + k0 + c4);
        }
    };
    auto sts_x = [&](int s) {
        char* aH = smem + s * STAGE;
        char* aL = aH + A_SZ;
#pragma unroll
        for (int t = 0; t < 4; ++t) {
            const int i = tid + t * NTHREADS;
            const int r = i >> 4, c4 = (i & 15) << 2;
            const float4 v = xv[t];
            __nv_bfloat16 h0 = __float2bfloat16(v.x), h1 = __float2bfloat16(v.y);
            __nv_bfloat16 h2 = __float2bfloat16(v.z), h3 = __float2bfloat16(v.w);
            float l0 = v.x - __bfloat162float(h0), l1 = v.y - __bfloat162float(h1);
            float l2 = v.z - __bfloat162float(h2), l3 = v.w - __bfloat162float(h3);
            const uint32_t off = sw128((uint32_t)(r * 128 + c4 * 2));
            *reinterpret_cast<uint2*>(aH + off) =
                make_uint2(pack_bf2(h0, h1), pack_bf2(h2, h3));
            *reinterpret_cast<uint2*>(aL + off) =
                make_uint2(pack_bf2(__float2bfloat16(l0), __float2bfloat16(l1)),
                           pack_bf2(__float2bfloat16(l2), __float2bfloat16(l3)));
        }
    };
    auto cpasync_w = [&](int s, int k0) {
        const uint32_t bH = sb + s * STAGE + 2 * A_SZ;
        const uint32_t bL = bH + B_SZ;
#pragma unroll
        for (int t = 0; t < 4; ++t) {
            const int i = tid + t * NTHREADS;
            const int r = i >> 3, c16 = (i & 7) << 4;
            const uint32_t off = sw128((uint32_t)(r * 128 + c16));
            const size_t gs = ((size_t)r * DIM + k0) * 2 + c16;
            cp_async16(bH + off, (const char*)g_w_hi + gs);
            cp_async16(bL + off, (const char*)g_w_lo + gs);
        }
        cp_commit();
    };
    auto compute = [&](int s) {
        const uint32_t aHb = sb + s * STAGE;
        const uint32_t aLb = aHb + A_SZ;
        const uint32_t bHb = aHb + 2 * A_SZ;
        const uint32_t bLb = bHb + B_SZ;
#pragma unroll
        for (int k = 0; k < 4; ++k) {
            const int kb = k * 32;
            uint32_t aH[2][4], aL[2][4];
#pragma unroll
            for (int mi = 0; mi < 2; ++mi) {
                const int row = wm * 32 + mi * 16 + (lane & 15);
                const int byt = ((lane >> 4) << 4) + kb;
                const uint32_t off = sw128((uint32_t)(row * 128 + byt));
                ldsm4(aH[mi], aHb + off);
                ldsm4(aL[mi], aLb + off);
            }
#pragma unroll
            for (int t = 0; t < 4; ++t) {
                const int nrow = wn * 64 + t * 16 + (lane & 7) + ((lane >> 4) << 3);
                const int byt  = kb + (((lane >> 3) & 1) << 4);
                const uint32_t off = sw128((uint32_t)(nrow * 128 + byt));
                uint32_t bH[4], bL[4];
                ldsm4(bH, bHb + off);
                ldsm4(bL, bLb + off);
                // Chain-outer order: dependent writes to the same accumulator
                // are 4 MMAs apart (hh -> hl -> lh), 4 independent streams each.
                mma_bf16(acc[0][2 * t],     aH[0], bH[0], bH[1]);  // hi*hi
                mma_bf16(acc[0][2 * t + 1], aH[0], bH[2], bH[3]);
                mma_bf16(acc[1][2 * t],     aH[1], bH[0], bH[1]);
                mma_bf16(acc[1][2 * t + 1], aH[1], bH[2], bH[3]);
                mma_bf16(acc[0][2 * t],     aH[0], bL[0], bL[1]);  // hi*lo
                mma_bf16(acc[0][2 * t + 1], aH[0], bL[2], bL[3]);
                mma_bf16(acc[1][2 * t],     aH[1], bL[0], bL[1]);
                mma_bf16(acc[1][2 * t + 1], aH[1], bL[2], bL[3]);
                mma_bf16(acc[0][2 * t],     aL[0], bH[0], bH[1]);  // lo*hi
                mma_bf16(acc[0][2 * t + 1], aL[0], bH[2], bH[3]);
                mma_bf16(acc[1][2 * t],     aL[1], bH[0], bH[1]);
                mma_bf16(acc[1][2 * t + 1], aL[1], bH[2], bH[3]);
            }
        }
    };

    // ---- pipelined mainloop ----
    // iter c: [cp.wait(w chunk c) | STS x(s) | bar | cp.async w(c+1) | LDG x(c+1) | MMA(s)]
    load_x(0);
    cpasync_w(0, 0);
    for (int c = 0; c < NCHUNK; ++c) {
        const int s = c & 1;
        cp_wait_all();                    // w for chunk c resident
        sts_x(s);
        __syncthreads();
        if (c + 1 < NCHUNK) {
            cpasync_w(s ^ 1, (c + 1) * KC);
            load_x((c + 1) * KC);
        }
        compute(s);
    }

    // ---- epilogue: scores -> smem, per-token argmax + exact rescore ----
    __syncthreads();
    float* sc = reinterpret_cast<float*>(smem);
#pragma unroll
    for (int mi = 0; mi < 2; ++mi)
#pragma unroll
        for (int nj = 0; nj < 8; ++nj) {
            const int r  = wm * 32 + mi * 16 + (lane >> 2);
            const int cc = wn * 64 + nj * 8 + ((lane & 3) << 1);
            sc[r * SC_STRIDE + cc]           = acc[mi][nj][0];
            sc[r * SC_STRIDE + cc + 1]       = acc[mi][nj][1];
            sc[(r + 8) * SC_STRIDE + cc]     = acc[mi][nj][2];
            sc[(r + 8) * SC_STRIDE + cc + 1] = acc[mi][nj][3];
        }
    __syncthreads();

    if (wid < 4) {
        const int r = wid * 32 + lane;     // token row in tile
        const int t = t0 + r;
        float m1 = -__int_as_float(0x7f800000);
        float m2 = m1;
        int i1 = 0;
        for (int j = 0; j < NEXP; ++j) {
            const float v = sc[r * SC_STRIDE + j];
            if (v > m1) { m2 = m1; m1 = v; i1 = j; }
            else if (v > m2) { m2 = v; }
        }
        if (m1 - m2 < TAU) {
            // exact fp32 rescore of all candidates within TAU of max
            float best = m1;
            int bi = i1;
            bool have = false;
            const float4* xa = reinterpret_cast<const float4*>(x + (size_t)t * DIM);
            for (int j = 0; j < NEXP; ++j) {
                if (sc[r * SC_STRIDE + j] >= m1 - TAU) {
                    const float4* wb =
                        reinterpret_cast<const float4*>(w + (size_t)j * DIM);
                    float s0 = 0.f, s1 = 0.f, s2 = 0.f, s3 = 0.f;
                    for (int kk = 0; kk < DIM / 4; ++kk) {
                        float4 va = xa[kk], vb = wb[kk];
                        s0 = fmaf(va.x, vb.x, s0);
                        s1 = fmaf(va.y, vb.y, s1);
                        s2 = fmaf(va.z, vb.z, s2);
                        s3 = fmaf(va.w, vb.w, s3);
                    }
                    const float ex = (s0 + s1) + (s2 + s3);
                    if (!have || ex > best) { have = true; best = ex; bi = j; }
                }
            }
            i1 = bi;
        }
        out[t]         = 1.0f;
        out[T_TOK + t] = (float)i1;
    }
}

extern "C" void kernel_launch(void* const* d_in, const int* in_sizes, int n_in,
                              void* d_out, int out_size) {
    const float* x = (const float*)d_in[0];   // [16384, 4096] f32
    const float* w = (const float*)d_in[1];   // [256, 4096]  f32
    (void)in_sizes; (void)n_in; (void)out_size;

    cudaFuncSetAttribute(gate_mma_kernel,
                         cudaFuncAttributeMaxDynamicSharedMemorySize, SMEM_TOTAL);

    wconv_kernel<<<256, 256>>>(w);
    gate_mma_kernel<<<T_TOK / BM, NTHREADS, SMEM_TOTAL>>>(x, w, (float*)d_out);
}

// round 8
// speedup vs baseline: 4.5497x; 2.0728x over previous
#include <cuda_runtime.h>
#include <cuda_bf16.h>
#include <cstdint>

// Gate_8108898255611 — router gate, single-chain bf16 mma.sync + exact rescore.
//   out[0:T)  = 1.0f (STE forward == one-hot)
//   out[T:2T) = argmax_e <x_t, w_e> as float
// Scores computed once in bf16 (round-nearest) with fp32 accumulation.
// Quantization error sigma ~2e-3; any token with top1-top2 gap < TAU=0.02 is
// exactly rescored in fp32 (warp-cooperative), making the argmax exact.

constexpr int T_TOK = 16384;
constexpr int DIM   = 4096;
constexpr int NEXP  = 256;
constexpr int BM    = 128;            // tokens per CTA
constexpr int KC    = 64;             // k per chunk (128B bf16 rows)
constexpr int NCHUNK = DIM / KC;      // 64
constexpr int NSTAGES = 4;
constexpr int NTHREADS = 512;         // 16 warps, 4x4 warp grid
constexpr float TAU = 0.02f;

constexpr int A_SZ  = BM * 128;       // 16KB (128 rows x 128B bf16)
constexpr int B_SZ  = NEXP * 128;     // 32KB
constexpr int STAGE = A_SZ + B_SZ;    // 48KB
constexpr int SMEM_TOTAL = NSTAGES * STAGE;   // 192KB
constexpr int SC_STRIDE = 257;

__device__ __nv_bfloat16 g_w_bf[NEXP * DIM];

// ---------------- helpers ----------------
__device__ __forceinline__ uint32_t smem_u32(const void* p) {
    uint32_t a;
    asm("{ .reg .u64 t; cvta.to.shared.u64 t, %1; cvt.u32.u64 %0, t; }"
        : "=r"(a) : "l"(p));
    return a;
}
__device__ __forceinline__ uint32_t sw128(uint32_t off) {
    return off ^ ((off >> 3) & 0x70);
}
__device__ __forceinline__ uint32_t pack_bf2(__nv_bfloat16 a, __nv_bfloat16 b) {
    return (uint32_t)__bfloat16_as_ushort(a) | ((uint32_t)__bfloat16_as_ushort(b) << 16);
}
__device__ __forceinline__ void ldsm4(uint32_t* r, uint32_t addr) {
    asm("ldmatrix.sync.aligned.m8n8.x4.shared.b16 {%0,%1,%2,%3}, [%4];"
        : "=r"(r[0]), "=r"(r[1]), "=r"(r[2]), "=r"(r[3]) : "r"(addr) : "memory");
}
__device__ __forceinline__ void mma_bf16(float* d, const uint32_t* a,
                                         uint32_t b0, uint32_t b1) {
    asm("mma.sync.aligned.m16n8k16.row.col.f32.bf16.bf16.f32 "
        "{%0,%1,%2,%3}, {%4,%5,%6,%7}, {%8,%9}, {%0,%1,%2,%3};"
        : "+f"(d[0]), "+f"(d[1]), "+f"(d[2]), "+f"(d[3])
        : "r"(a[0]), "r"(a[1]), "r"(a[2]), "r"(a[3]), "r"(b0), "r"(b1));
}
__device__ __forceinline__ void cp_async16(uint32_t dst, const void* src) {
    asm volatile("cp.async.cg.shared.global [%0], [%1], 16;"
                 :: "r"(dst), "l"(src) : "memory");
}
__device__ __forceinline__ void cp_commit() {
    asm volatile("cp.async.commit_group;" ::: "memory");
}
__device__ __forceinline__ void cp_wait2() {
    asm volatile("cp.async.wait_group 2;" ::: "memory");
}

// ---------------- w pre-convert (round-nearest bf16) ----------------
__global__ void wconv_kernel(const float* __restrict__ w) {
    int n4 = NEXP * DIM / 4;
    for (int i = blockIdx.x * blockDim.x + threadIdx.x; i < n4;
         i += gridDim.x * blockDim.x) {
        float4 v = reinterpret_cast<const float4*>(w)[i];
        reinterpret_cast<uint2*>(g_w_bf)[i] =
            make_uint2(pack_bf2(__float2bfloat16(v.x), __float2bfloat16(v.y)),
                       pack_bf2(__float2bfloat16(v.z), __float2bfloat16(v.w)));
    }
}

// ---------------- main kernel ----------------
__global__ __launch_bounds__(NTHREADS, 1)
void gate_mma_kernel(const float* __restrict__ x,
                     const float* __restrict__ w,
                     float* __restrict__ out)
{
    extern __shared__ char smem[];
    __shared__ int   s_cnt;
    __shared__ int   s_list[BM];
    __shared__ float s_m1[BM];
    const uint32_t sb = smem_u32(smem);
    const int tid  = threadIdx.x;
    const int lane = tid & 31;
    const int wid  = tid >> 5;
    const int wm   = wid >> 2;   // 0..3 -> 32-row strip
    const int wn   = wid & 3;    // 0..3 -> 64-col strip
    const int t0   = blockIdx.x * BM;
    const float* xbase = x + (size_t)t0 * DIM;

    if (tid == 0) s_cnt = 0;

    float acc[2][8][4];
#pragma unroll
    for (int i = 0; i < 2; i++)
#pragma unroll
        for (int j = 0; j < 8; j++)
#pragma unroll
            for (int q = 0; q < 4; q++) acc[i][j][q] = 0.f;

    float4 xv[4];  // prefetched x chunk (fp32)

    auto load_x = [&](int k0) {
#pragma unroll
        for (int t = 0; t < 4; ++t) {
            const int i = tid + t * NTHREADS;
            const int r = i >> 4, c4 = (i & 15) << 2;
            xv[t] = *reinterpret_cast<const float4*>(xbase + (size_t)r * DIM + k0 + c4);
        }
    };
    auto sts_x = [&](int s) {
        char* aB = smem + s * STAGE;
#pragma unroll
        for (int t = 0; t < 4; ++t) {
            const int i = tid + t * NTHREADS;
            const int r = i >> 4, c4 = (i & 15) << 2;
            const float4 v = xv[t];
            const uint32_t off = sw128((uint32_t)(r * 128 + c4 * 2));
            *reinterpret_cast<uint2*>(aB + off) =
                make_uint2(pack_bf2(__float2bfloat16(v.x), __float2bfloat16(v.y)),
                           pack_bf2(__float2bfloat16(v.z), __float2bfloat16(v.w)));
        }
    };
    auto cpasync_w = [&](int s, int k0) {
        const uint32_t bB = sb + s * STAGE + A_SZ;
#pragma unroll
        for (int t = 0; t < 4; ++t) {
            const int i = tid + t * NTHREADS;
            const int r = i >> 3, c16 = (i & 7) << 4;
            const uint32_t off = sw128((uint32_t)(r * 128 + c16));
            const size_t gs = ((size_t)r * DIM + k0) * 2 + c16;
            cp_async16(bB + off, (const char*)g_w_bf + gs);
        }
    };
    auto compute = [&](int s) {
        const uint32_t aB = sb + s * STAGE;
        const uint32_t bB = aB + A_SZ;
#pragma unroll
        for (int k = 0; k < 4; ++k) {
            const int kb = k * 32;
            uint32_t a[2][4];
#pragma unroll
            for (int mi = 0; mi < 2; ++mi) {
                const int row = wm * 32 + mi * 16 + (lane & 15);
                const int byt = ((lane >> 4) << 4) + kb;
                ldsm4(a[mi], aB + sw128((uint32_t)(row * 128 + byt)));
            }
#pragma unroll
            for (int t = 0; t < 4; ++t) {
                const int nrow = wn * 64 + t * 16 + (lane & 7) + ((lane >> 4) << 3);
                const int byt  = kb + (((lane >> 3) & 1) << 4);
                uint32_t b[4];
                ldsm4(b, bB + sw128((uint32_t)(nrow * 128 + byt)));
                // 4 independent accumulators per t-block
                mma_bf16(acc[0][2 * t],     a[0], b[0], b[1]);
                mma_bf16(acc[0][2 * t + 1], a[0], b[2], b[3]);
                mma_bf16(acc[1][2 * t],     a[1], b[0], b[1]);
                mma_bf16(acc[1][2 * t + 1], a[1], b[2], b[3]);
            }
        }
    };

    // ---- pipelined mainloop: 4 stages, w prefetched 3 chunks deep ----
    // chunk c lives in commit-group #(c+1); before compute(c) we wait_group 2
    // with (3+c) groups committed -> group c+1 complete. Empty commits at the
    // tail keep the arithmetic exact.
    load_x(0);
    cpasync_w(0, 0);      cp_commit();
    cpasync_w(1, KC);     cp_commit();
    cpasync_w(2, 2 * KC); cp_commit();
    for (int c = 0; c < NCHUNK; ++c) {
        const int s = c & (NSTAGES - 1);
        cp_wait2();                       // w chunk c resident
        sts_x(s);
        __syncthreads();                  // stage s fully built; compute(c-1) done
        if (c + 3 < NCHUNK) cpasync_w((c + 3) & (NSTAGES - 1), (c + 3) * KC);
        cp_commit();                      // always commit (possibly empty group)
        if (c + 1 < NCHUNK) load_x((c + 1) * KC);
        compute(s);
    }

    // ---- epilogue: scores -> smem, argmax, cooperative exact rescore ----
    __syncthreads();
    float* sc = reinterpret_cast<float*>(smem);
#pragma unroll
    for (int mi = 0; mi < 2; ++mi)
#pragma unroll
        for (int nj = 0; nj < 8; ++nj) {
            const int r  = wm * 32 + mi * 16 + (lane >> 2);
            const int cc = wn * 64 + nj * 8 + ((lane & 3) << 1);
            sc[r * SC_STRIDE + cc]           = acc[mi][nj][0];
            sc[r * SC_STRIDE + cc + 1]       = acc[mi][nj][1];
            sc[(r + 8) * SC_STRIDE + cc]     = acc[mi][nj][2];
            sc[(r + 8) * SC_STRIDE + cc + 1] = acc[mi][nj][3];
        }
    __syncthreads();

    // Phase 1: per-token scan; clear winners written directly, near-ties queued.
    if (wid < 4) {
        const int r = wid * 32 + lane;
        const int t = t0 + r;
        float m1 = -__int_as_float(0x7f800000);
        float m2 = m1;
        int i1 = 0;
        for (int j = 0; j < NEXP; ++j) {
            const float v = sc[r * SC_STRIDE + j];
            if (v > m1) { m2 = m1; m1 = v; i1 = j; }
            else if (v > m2) { m2 = v; }
        }
        out[t] = 1.0f;
        if (m1 - m2 >= TAU) {
            out[T_TOK + t] = (float)i1;
        } else {
            const int p = atomicAdd(&s_cnt, 1);
            s_list[p] = r;
            s_m1[p]   = m1;
        }
    }
    __syncthreads();

    // Phase 2: warp-cooperative exact fp32 rescore of queued tokens.
    const int cnt = s_cnt;
    for (int q = wid; q < cnt; q += 16) {
        const int r  = s_list[q];
        const float m1 = s_m1[q];
        const int t  = t0 + r;
        float best = -__int_as_float(0x7f800000);
        int   bi   = 0;
        const float4* xa = reinterpret_cast<const float4*>(x + (size_t)t * DIM);
        for (int e0 = 0; e0 < NEXP; e0 += 32) {
            const bool cand = sc[r * SC_STRIDE + e0 + lane] >= m1 - TAU;
            unsigned msk = __ballot_sync(0xffffffffu, cand);
            while (msk) {
                const int e = e0 + (__ffs(msk) - 1);
                msk &= msk - 1;
                const float4* wb = reinterpret_cast<const float4*>(w + (size_t)e * DIM);
                float s0 = 0.f, s1 = 0.f, s2 = 0.f, s3 = 0.f;
                for (int k = lane; k < DIM / 4; k += 32) {
                    float4 va = xa[k], vb = wb[k];
                    s0 = fmaf(va.x, vb.x, s0);
                    s1 = fmaf(va.y, vb.y, s1);
                    s2 = fmaf(va.z, vb.z, s2);
                    s3 = fmaf(va.w, vb.w, s3);
                }
                float ssum = (s0 + s1) + (s2 + s3);
#pragma unroll
                for (int off = 16; off > 0; off >>= 1)
                    ssum += __shfl_xor_sync(0xffffffffu, ssum, off);
                // candidates visited in ascending e: strict > keeps lowest index
                if (ssum > best) { best = ssum; bi = e; }
            }
        }
        if (lane == 0) out[T_TOK + t] = (float)bi;
    }
}

extern "C" void kernel_launch(void* const* d_in, const int* in_sizes, int n_in,
                              void* d_out, int out_size) {
    const float* x = (const float*)d_in[0];   // [16384, 4096] f32
    const float* w = (const float*)d_in[1];   // [256, 4096]  f32
    (void)in_sizes; (void)n_in; (void)out_size;

    cudaFuncSetAttribute(gate_mma_kernel,
                         cudaFuncAttributeMaxDynamicSharedMemorySize, SMEM_TOTAL);

    wconv_kernel<<<256, 256>>>(w);
    gate_mma_kernel<<<T_TOK / BM, NTHREADS, SMEM_TOTAL>>>(x, w, (float*)d_out);
}